// round 15
// baseline (speedup 1.0000x reference)
#include <cuda_runtime.h>
#include <cuda_fp16.h>
#include <cstdint>

#define NN   4096
#define DIN  512
#define HID  256
#define DBOX 22

// ---- scratch (device globals) ----
__device__ __half g_xb[NN * DIN];
__device__ __half g_Wb[6][DIN * HID];    // W in f16, [k][n] as given
__device__ __half g_Kb[2][NN * HID];
__device__ __half g_Qb[2][NN * HID];
__device__ __half g_Vb[2][NN * HID];
__device__ __half g_BMb[2][NN * 32];     // box@M, zero-padded to 32 cols
__device__ __half g_boxb[NN * 32];       // box, zero-padded to 32 cols
__device__ float g_M[2][DBOX * DBOX];
__device__ float g_O[2][NN * HID];
__device__ float g_part[2][64];

// ================= PTX helpers =====================================================
__device__ __forceinline__ uint32_t s2u(const void* p) {
    uint32_t a;
    asm("{ .reg .u64 t; cvta.to.shared.u64 t, %1; cvt.u32.u64 %0, t; }" : "=r"(a) : "l"(p));
    return a;
}
__device__ __forceinline__ void cp16(uint32_t s, const void* g) {
    asm volatile("cp.async.cg.shared.global [%0], [%1], 16;" :: "r"(s), "l"(g));
}
#define CP_COMMIT asm volatile("cp.async.commit_group;" ::: "memory")
#define CP_WAIT0  asm volatile("cp.async.wait_group 0;"  ::: "memory")
#define CP_WAIT1  asm volatile("cp.async.wait_group 1;"  ::: "memory")

__device__ __forceinline__ void ldsm4(uint32_t* r, uint32_t a) {
    asm volatile("ldmatrix.sync.aligned.m8n8.x4.shared.b16 {%0,%1,%2,%3}, [%4];"
                 : "=r"(r[0]), "=r"(r[1]), "=r"(r[2]), "=r"(r[3]) : "r"(a));
}
__device__ __forceinline__ void ldsm4t(uint32_t* r, uint32_t a) {
    asm volatile("ldmatrix.sync.aligned.m8n8.x4.trans.shared.b16 {%0,%1,%2,%3}, [%4];"
                 : "=r"(r[0]), "=r"(r[1]), "=r"(r[2]), "=r"(r[3]) : "r"(a));
}
// f16 x f16 -> f16 acc (packed half2 accumulators, 2 regs)
__device__ __forceinline__ void mma16816h(uint32_t* d, const uint32_t* a, const uint32_t* b) {
    asm volatile(
        "mma.sync.aligned.m16n8k16.row.col.f16.f16.f16.f16 "
        "{%0,%1}, {%2,%3,%4,%5}, {%6,%7}, {%0,%1};"
        : "+r"(d[0]), "+r"(d[1])
        : "r"(a[0]), "r"(a[1]), "r"(a[2]), "r"(a[3]), "r"(b[0]), "r"(b[1]));
}
__device__ __forceinline__ uint32_t packh2(float x, float y) {
    __half2 h = __floats2half2_rn(x, y);
    return *(uint32_t*)&h;
}
__device__ __forceinline__ float2 unpackh2(uint32_t u) {
    return __half22float2(*(__half2*)&u);
}

// ================= conversions (known-good, separate launches) ====================
__global__ __launch_bounds__(256) void conv_x(const float* __restrict__ x) {
    int idx = blockIdx.x * 256 + threadIdx.x;          // float4 index
    float4 v = ((const float4*)x)[idx];
    *(uint32_t*)&g_xb[idx * 4]     = packh2(v.x, v.y);
    *(uint32_t*)&g_xb[idx * 4 + 2] = packh2(v.z, v.w);
}

__global__ __launch_bounds__(256) void conv_w(
    const float* __restrict__ W0, const float* __restrict__ W1, const float* __restrict__ W2,
    const float* __restrict__ W3, const float* __restrict__ W4, const float* __restrict__ W5) {
    const int z = blockIdx.z;
    const float* W = (z == 0) ? W0 : (z == 1) ? W1 : (z == 2) ? W2 : (z == 3) ? W3 : (z == 4) ? W4 : W5;
    int idx = blockIdx.x * 256 + threadIdx.x;
    float4 v = ((const float4*)W)[idx];
    *(uint32_t*)&g_Wb[z][idx * 4]     = packh2(v.x, v.y);
    *(uint32_t*)&g_Wb[z][idx * 4 + 2] = packh2(v.z, v.w);
}

// ================= M = WG @ WG^T (22x22, fp32) ====================================
__global__ void gramm_kernel(const float* __restrict__ WG1, const float* __restrict__ WG2) {
    const float* WG = blockIdx.x ? WG2 : WG1;
    int t = threadIdx.x;
    if (t < DBOX * DBOX) {
        int i = t / DBOX, j = t % DBOX;
        float s = 0.f;
        for (int d = 0; d < HID; ++d) s += WG[i * HID + d] * WG[j * HID + d];
        g_M[blockIdx.x][t] = s;
    }
}

// ================= pad box / BM -> [4096,32] f16 ==================================
__global__ __launch_bounds__(256) void pad_kernel(const float* __restrict__ box) {
    __shared__ float Ms[DBOX * DBOX];
    int y = blockIdx.y, t = threadIdx.x;   // y: 0=box, 1=BM br0, 2=BM br1
    if (y > 0) {
        for (int i = t; i < DBOX * DBOX; i += 256) Ms[i] = g_M[y - 1][i];
        __syncthreads();
    }
    int e = blockIdx.x * 256 + t;          // 4096*32 total, grid.x = 512
    int r = e >> 5, c = e & 31;
    float v = 0.f;
    if (c < DBOX) {
        if (y == 0) v = box[r * DBOX + c];
        else {
            float s = 0.f;
#pragma unroll
            for (int k = 0; k < DBOX; ++k) s += box[r * DBOX + k] * Ms[k * DBOX + c];
            v = s;
        }
    }
    __half h = __float2half(v);
    if (y == 0) g_boxb[e] = h;
    else g_BMb[y - 1][e] = h;
}

// ================= projection: C[4096,256] = xb @ W  (mma.sync f16) ===============
__global__ void __launch_bounds__(256, 1) proj_kernel(int) {
    extern __shared__ char smem[];
    const int z = blockIdx.z;
    const int m0 = blockIdx.x * 128, n0 = blockIdx.y * 64;
    const int br = z / 3, wh = z % 3;
    __half* C = (wh == 0) ? g_Kb[br] : (wh == 1) ? g_Qb[br] : g_Vb[br];
    const __half* __restrict__ Wb = g_Wb[z];
    const int t = threadIdx.x, w = t >> 5, lane = t & 31;
    uint32_t sb = s2u(smem);
    const int mi = w >> 1, njw = w & 1;
    uint32_t acc[2][4][2] = {};

#define PROJ_ISSUE(ck)                                                               \
    {                                                                                \
        int k0 = (ck) * 64, buf = (ck) & 1;                                          \
        _Pragma("unroll") for (int l = 0; l < 4; ++l) {                              \
            int idx = t + l * 256;                                                   \
            int r = idx >> 3, c8 = (idx & 7) << 3;                                   \
            cp16(sb + buf * 18432 + (r * 72 + c8) * 2, g_xb + (m0 + r) * DIN + k0 + c8); \
        }                                                                            \
        _Pragma("unroll") for (int l = 0; l < 2; ++l) {                              \
            int idx = t + l * 256;                                                   \
            int r = idx >> 3, c8 = (idx & 7) << 3;                                   \
            cp16(sb + 36864 + buf * 9216 + (r * 72 + c8) * 2, Wb + (k0 + r) * HID + n0 + c8); \
        }                                                                            \
        CP_COMMIT;                                                                   \
    }

    PROJ_ISSUE(0);
    for (int ck = 0; ck < 8; ++ck) {
        if (ck < 7) { PROJ_ISSUE(ck + 1); CP_WAIT1; } else { CP_WAIT0; }
        __syncthreads();
        const uint32_t aB = sb + (ck & 1) * 18432;
        const uint32_t bB = sb + 36864 + (ck & 1) * 9216;
#pragma unroll
        for (int kt = 0; kt < 4; ++kt) {
            uint32_t a[2][4];
#pragma unroll
            for (int mt = 0; mt < 2; ++mt) {
                int row = mi * 32 + mt * 16 + (lane & 15);
                int col = kt * 16 + ((lane >> 4) << 3);
                ldsm4(a[mt], aB + (row * 72 + col) * 2);
            }
#pragma unroll
            for (int nb = 0; nb < 2; ++nb) {
                uint32_t bw[4];
                int wrow = kt * 16 + ((lane >> 3) & 1) * 8 + (lane & 7);
                int wcol = njw * 32 + nb * 16 + ((lane >> 4) << 3);
                ldsm4t(bw, bB + (wrow * 72 + wcol) * 2);
#pragma unroll
                for (int mt = 0; mt < 2; ++mt) {
                    mma16816h(acc[mt][nb * 2],     a[mt], bw);
                    mma16816h(acc[mt][nb * 2 + 1], a[mt], bw + 2);
                }
            }
        }
        __syncthreads();
    }
#pragma unroll
    for (int mt = 0; mt < 2; ++mt)
#pragma unroll
        for (int nt = 0; nt < 4; ++nt) {
            int row = m0 + mi * 32 + mt * 16 + (lane >> 2);
            int col = n0 + njw * 32 + nt * 8 + (lane & 3) * 2;
            *(uint32_t*)&C[row * HID + col]       = acc[mt][nt][0];
            *(uint32_t*)&C[(row + 8) * HID + col] = acc[mt][nt][1];
        }
}

// ================= fused attention: 64-row tiles, hoisted K/BM A-fragments ========
// (exact R12 structure — best measured configuration)
// 8 warps: mi = w>>1 (m16 rows), jh2 = w&1 (j32 k-slice in both GEMMs).
// smem map (bytes):
//   sK   [64][264] @0        33792
//   sBM  [64][40]  @33792     5120
//   sQ 2x[64][264] @38912    67584   (reused as O-reduce buffer [64][256] f32)
//   sBox 2x[64][40]@106496   10240
//   sV 2x[64][264] @116736   67584
//   sred           @184320    1024   -> total 185344
__global__ void __launch_bounds__(256, 1) attn_kernel(int) {
    extern __shared__ char smem[];
    const int b = blockIdx.y;
    const int i0 = blockIdx.x * 64;
    const int t = threadIdx.x, w = t >> 5, lane = t & 31;
    uint32_t sb = s2u(smem);
    const __half* __restrict__ Kg = g_Kb[b];
    const __half* __restrict__ Qg = g_Qb[b];
    const __half* __restrict__ Vg = g_Vb[b];
    const __half* __restrict__ BMg = g_BMb[b];

    const int mi = w >> 1, jh2 = w & 1;
    uint32_t acc[32][2] = {};       // O-partial: m16 x d256 (f16 packed)
    uint32_t ka[16][4];             // hoisted K A-frags: m16 x k256
    uint32_t agm[2][4];             // hoisted BM A-frags: m16 x k32
    float sumLoc = 0.f;

    // ---- prologue loads ----
#pragma unroll
    for (int l = 0; l < 8; ++l) {
        int idx = t + l * 256;
        int r = idx >> 5, c8 = (idx & 31) << 3;
        cp16(sb + (r * 264 + c8) * 2, Kg + (i0 + r) * HID + c8);
    }
    { int r = t >> 2, c8 = (t & 3) << 3;
      cp16(sb + 33792 + (r * 40 + c8) * 2, BMg + (i0 + r) * 32 + c8); }
    CP_COMMIT;

#define ATTN_ISSUE(j0, buf)                                                          \
    {                                                                                \
        _Pragma("unroll") for (int l = 0; l < 8; ++l) {                              \
            int idx = t + l * 256;                                                   \
            int r = idx >> 5, c8 = (idx & 31) << 3;                                  \
            cp16(sb + 38912 + (buf) * 33792 + (r * 264 + c8) * 2, Qg + ((j0) + r) * HID + c8); \
        }                                                                            \
        _Pragma("unroll") for (int l = 0; l < 8; ++l) {                              \
            int idx = t + l * 256;                                                   \
            int r = idx >> 5, c8 = (idx & 31) << 3;                                  \
            cp16(sb + 116736 + (buf) * 33792 + (r * 264 + c8) * 2, Vg + ((j0) + r) * HID + c8); \
        }                                                                            \
        { int r = t >> 2, c8 = (t & 3) << 3;                                         \
          cp16(sb + 106496 + (buf) * 5120 + (r * 40 + c8) * 2, g_boxb + ((j0) + r) * 32 + c8); } \
        CP_COMMIT;                                                                   \
    }
    ATTN_ISSUE(0, 0);
    ATTN_ISSUE(64, 1);

#pragma unroll 1
    for (int jt = 0; jt < 64; ++jt) {
        const int cur = jt & 1;
        CP_WAIT1;                  // tiles for jt (and K/BM on jt=0) resident
        __syncthreads();
        const uint32_t qB = sb + 38912 + cur * 33792;
        const uint32_t xB = sb + 106496 + cur * 5120;
        const uint32_t vB = sb + 116736 + cur * 33792;

        if (jt == 0) {             // hoist K + BM A-frags into persistent registers
#pragma unroll
            for (int kt = 0; kt < 16; ++kt) {
                int row = mi * 16 + (lane & 15);
                int col = kt * 16 + ((lane >> 4) << 3);
                ldsm4(ka[kt], sb + (row * 264 + col) * 2);
            }
#pragma unroll
            for (int kt = 0; kt < 2; ++kt) {
                int row = mi * 16 + (lane & 15);
                int col = kt * 16 + ((lane >> 4) << 3);
                ldsm4(agm[kt], sb + 33792 + (row * 40 + col) * 2);
            }
        }

        // ---- stage 1: wa = K_i . Q_j^T (k=256), A from registers ----
        uint32_t wa[4][2] = {};
        uint32_t gg[4][2] = {};
        const int brow = jh2 * 32 + ((lane >> 4) << 3) + (lane & 7);
#pragma unroll
        for (int kt = 0; kt < 16; ++kt) {
            uint32_t bq0[4], bq1[4];
            int bcol = kt * 16 + ((lane >> 3) & 1) * 8;
            ldsm4(bq0, qB + (brow * 264 + bcol) * 2);
            ldsm4(bq1, qB + ((brow + 16) * 264 + bcol) * 2);
            mma16816h(wa[0], ka[kt], bq0);
            mma16816h(wa[1], ka[kt], bq0 + 2);
            mma16816h(wa[2], ka[kt], bq1);
            mma16816h(wa[3], ka[kt], bq1 + 2);
        }
        // ---- gate: gg = BM_i . box_j^T (k=32), A from registers ----
#pragma unroll
        for (int kt = 0; kt < 2; ++kt) {
            uint32_t bx0[4], bx1[4];
            int bcol = kt * 16 + ((lane >> 3) & 1) * 8;
            ldsm4(bx0, xB + (brow * 40 + bcol) * 2);
            ldsm4(bx1, xB + ((brow + 16) * 40 + bcol) * 2);
            mma16816h(gg[0], agm[kt], bx0);
            mma16816h(gg[1], agm[kt], bx0 + 2);
            mma16816h(gg[2], agm[kt], bx1);
            mma16816h(gg[3], agm[kt], bx1 + 2);
        }

        // ---- elementwise in regs: S = relu(G/16) * exp(WA/16); pack to A-frags ----
        uint32_t sf[2][4];
#pragma unroll
        for (int nb = 0; nb < 4; ++nb) {
            float2 a01 = unpackh2(wa[nb][0]), a23 = unpackh2(wa[nb][1]);
            float2 g01 = unpackh2(gg[nb][0]), g23 = unpackh2(gg[nb][1]);
            float s0 = g01.x > 0.f ? g01.x * 0.0625f * __expf(a01.x * 0.0625f) : 0.f;
            float s1 = g01.y > 0.f ? g01.y * 0.0625f * __expf(a01.y * 0.0625f) : 0.f;
            float s2 = g23.x > 0.f ? g23.x * 0.0625f * __expf(a23.x * 0.0625f) : 0.f;
            float s3 = g23.y > 0.f ? g23.y * 0.0625f * __expf(a23.y * 0.0625f) : 0.f;
            sumLoc += (s0 + s1) + (s2 + s3);
            sf[nb >> 1][(nb & 1) * 2]     = packh2(s0, s1);
            sf[nb >> 1][(nb & 1) * 2 + 1] = packh2(s2, s3);
        }

        // ---- stage 2: O-partial += S(m16 x j32) @ V(j32 x d256) ----
#pragma unroll
        for (int kt2 = 0; kt2 < 2; ++kt2) {
            int vrow = jh2 * 32 + kt2 * 16 + ((lane >> 3) & 1) * 8 + (lane & 7);
#pragma unroll
            for (int nb = 0; nb < 16; ++nb) {
                uint32_t bv[4];
                int vcol = nb * 16 + ((lane >> 4) << 3);
                ldsm4t(bv, vB + (vrow * 264 + vcol) * 2);
                mma16816h(acc[nb * 2],     sf[kt2], bv);
                mma16816h(acc[nb * 2 + 1], sf[kt2], bv + 2);
            }
        }
        __syncthreads();           // all warps done with buf 'cur'
        ATTN_ISSUE(((jt + 2) & 63) * 64, cur);
    }

    // ---- epilogue: cross-pair O reduce (j-halves) via smem, write g_O ----
    CP_WAIT0;
    __syncthreads();
    float* smemO = (float*)(smem + 38912);    // [64][256] f32
    if (jh2 == 0) {
#pragma unroll
        for (int nb = 0; nb < 32; ++nb) {
            int row = mi * 16 + (lane >> 2);
            int col = nb * 8 + (lane & 3) * 2;
            *(float2*)&smemO[row * 256 + col]       = unpackh2(acc[nb][0]);
            *(float2*)&smemO[(row + 8) * 256 + col] = unpackh2(acc[nb][1]);
        }
    }
    __syncthreads();
    if (jh2 == 1) {
#pragma unroll
        for (int nb = 0; nb < 32; ++nb) {
            int row = mi * 16 + (lane >> 2);
            int col = nb * 8 + (lane & 3) * 2;
            float2 q0 = unpackh2(acc[nb][0]);
            float2 q1 = unpackh2(acc[nb][1]);
            float2 p0 = *(float2*)&smemO[row * 256 + col];
            float2 p1 = *(float2*)&smemO[(row + 8) * 256 + col];
            *(float2*)&g_O[b][(i0 + row) * HID + col] =
                make_float2(p0.x + q0.x, p0.y + q0.y);
            *(float2*)&g_O[b][(i0 + row + 8) * HID + col] =
                make_float2(p1.x + q1.x, p1.y + q1.y);
        }
    }

    // ---- deterministic partial sum ----
    float* sred = (float*)(smem + 184320);
    sred[t] = sumLoc;
    __syncthreads();
    for (int s2 = 128; s2 > 0; s2 >>= 1) {
        if (t < s2) sred[t] += sred[t + s2];
        __syncthreads();
    }
    if (t == 0) g_part[b][blockIdx.x] = sred[0];
}

// ================= out = x + 0.1 * O/sum (sum folded in, deterministic) ===========
__global__ __launch_bounds__(256) void final_kernel(const float* __restrict__ x,
                                                    float* __restrict__ out) {
    float s0 = 0.f, s1 = 0.f;
#pragma unroll
    for (int i = 0; i < 64; ++i) { s0 += g_part[0][i]; s1 += g_part[1][i]; }
    float is0 = 0.1f / s0, is1 = 0.1f / s1;
    int idx = blockIdx.x * 256 + threadIdx.x;
    int r = idx >> 9, c = idx & 511;
    int b = c >> 8, cc = c & 255;
    out[idx] = fmaf(g_O[b][r * HID + cc], b ? is1 : is0, x[idx]);
}

// =================================================================================
extern "C" void kernel_launch(void* const* d_in, const int* in_sizes, int n_in,
                              void* d_out, int out_size) {
    const float* x   = (const float*)d_in[0];
    const float* box = (const float*)d_in[1];
    const float* WG1 = (const float*)d_in[2];
    const float* WK1 = (const float*)d_in[3];
    const float* WQ1 = (const float*)d_in[4];
    const float* WV1 = (const float*)d_in[5];
    const float* WG2 = (const float*)d_in[6];
    const float* WK2 = (const float*)d_in[7];
    const float* WQ2 = (const float*)d_in[8];
    const float* WV2 = (const float*)d_in[9];
    float* out = (float*)d_out;

    static int inited = 0;
    if (!inited) {
        cudaFuncSetAttribute(proj_kernel, cudaFuncAttributeMaxDynamicSharedMemorySize, 55296);
        cudaFuncSetAttribute(attn_kernel, cudaFuncAttributeMaxDynamicSharedMemorySize, 185344);
        inited = 1;
    }

    conv_x<<<2048, 256>>>(x);
    conv_w<<<dim3(128, 1, 6), 256>>>(WK1, WQ1, WV1, WK2, WQ2, WV2);
    gramm_kernel<<<2, 512>>>(WG1, WG2);
    pad_kernel<<<dim3(512, 3), 256>>>(box);
    proj_kernel<<<dim3(32, 4, 6), 256, 55296>>>(0);
    attn_kernel<<<dim3(64, 2), 256, 185344>>>(0);
    final_kernel<<<8192, 256>>>(x, out);
}

// round 16
// speedup vs baseline: 1.6987x; 1.6987x over previous
#include <cuda_runtime.h>
#include <cuda_fp16.h>
#include <cstdint>

#define NN   4096
#define DIN  512
#define HID  256
#define DBOX 22

// ---- scratch (device globals) ----
__device__ __half g_xb[NN * DIN];
__device__ __half g_Wb[6][DIN * HID];    // W in f16, [k][n] as given
__device__ __half g_Kb[2][NN * HID];
__device__ __half g_Qb[2][NN * HID];
__device__ __half g_Vb[2][NN * HID];
__device__ __half g_BMb[2][NN * 32];     // box@M, zero-padded to 32 cols
__device__ __half g_boxb[NN * 32];       // box, zero-padded to 32 cols
__device__ float g_M[2][DBOX * DBOX];
__device__ float g_O[2][NN * HID];
__device__ float g_part[2][64];
__device__ float g_isum[2];

// ================= PTX helpers =====================================================
__device__ __forceinline__ uint32_t s2u(const void* p) {
    uint32_t a;
    asm("{ .reg .u64 t; cvta.to.shared.u64 t, %1; cvt.u32.u64 %0, t; }" : "=r"(a) : "l"(p));
    return a;
}
__device__ __forceinline__ void cp16(uint32_t s, const void* g) {
    asm volatile("cp.async.cg.shared.global [%0], [%1], 16;" :: "r"(s), "l"(g));
}
#define CP_COMMIT asm volatile("cp.async.commit_group;" ::: "memory")
#define CP_WAIT0  asm volatile("cp.async.wait_group 0;"  ::: "memory")
#define CP_WAIT1  asm volatile("cp.async.wait_group 1;"  ::: "memory")

__device__ __forceinline__ void ldsm4(uint32_t* r, uint32_t a) {
    asm volatile("ldmatrix.sync.aligned.m8n8.x4.shared.b16 {%0,%1,%2,%3}, [%4];"
                 : "=r"(r[0]), "=r"(r[1]), "=r"(r[2]), "=r"(r[3]) : "r"(a));
}
__device__ __forceinline__ void ldsm4t(uint32_t* r, uint32_t a) {
    asm volatile("ldmatrix.sync.aligned.m8n8.x4.trans.shared.b16 {%0,%1,%2,%3}, [%4];"
                 : "=r"(r[0]), "=r"(r[1]), "=r"(r[2]), "=r"(r[3]) : "r"(a));
}
// f16 x f16 -> f16 acc (packed half2 accumulators, 2 regs)
__device__ __forceinline__ void mma16816h(uint32_t* d, const uint32_t* a, const uint32_t* b) {
    asm volatile(
        "mma.sync.aligned.m16n8k16.row.col.f16.f16.f16.f16 "
        "{%0,%1}, {%2,%3,%4,%5}, {%6,%7}, {%0,%1};"
        : "+r"(d[0]), "+r"(d[1])
        : "r"(a[0]), "r"(a[1]), "r"(a[2]), "r"(a[3]), "r"(b[0]), "r"(b[1]));
}
__device__ __forceinline__ uint32_t packh2(float x, float y) {
    __half2 h = __floats2half2_rn(x, y);
    return *(uint32_t*)&h;
}
__device__ __forceinline__ float2 unpackh2(uint32_t u) {
    return __half22float2(*(__half2*)&u);
}

// ================= conversions (known-good, separate launches) ====================
__global__ __launch_bounds__(256) void conv_x(const float* __restrict__ x) {
    int idx = blockIdx.x * 256 + threadIdx.x;          // float4 index
    float4 v = ((const float4*)x)[idx];
    *(uint32_t*)&g_xb[idx * 4]     = packh2(v.x, v.y);
    *(uint32_t*)&g_xb[idx * 4 + 2] = packh2(v.z, v.w);
}

__global__ __launch_bounds__(256) void conv_w(
    const float* __restrict__ W0, const float* __restrict__ W1, const float* __restrict__ W2,
    const float* __restrict__ W3, const float* __restrict__ W4, const float* __restrict__ W5) {
    const int z = blockIdx.z;
    const float* W = (z == 0) ? W0 : (z == 1) ? W1 : (z == 2) ? W2 : (z == 3) ? W3 : (z == 4) ? W4 : W5;
    int idx = blockIdx.x * 256 + threadIdx.x;
    float4 v = ((const float4*)W)[idx];
    *(uint32_t*)&g_Wb[z][idx * 4]     = packh2(v.x, v.y);
    *(uint32_t*)&g_Wb[z][idx * 4 + 2] = packh2(v.z, v.w);
}

// ================= M = WG @ WG^T (22x22, fp32) ====================================
__global__ void gramm_kernel(const float* __restrict__ WG1, const float* __restrict__ WG2) {
    const float* WG = blockIdx.x ? WG2 : WG1;
    int t = threadIdx.x;
    if (t < DBOX * DBOX) {
        int i = t / DBOX, j = t % DBOX;
        float s = 0.f;
        for (int d = 0; d < HID; ++d) s += WG[i * HID + d] * WG[j * HID + d];
        g_M[blockIdx.x][t] = s;
    }
}

// ================= pad box / BM -> [4096,32] f16 ==================================
__global__ __launch_bounds__(256) void pad_kernel(const float* __restrict__ box) {
    __shared__ float Ms[DBOX * DBOX];
    int y = blockIdx.y, t = threadIdx.x;   // y: 0=box, 1=BM br0, 2=BM br1
    if (y > 0) {
        for (int i = t; i < DBOX * DBOX; i += 256) Ms[i] = g_M[y - 1][i];
        __syncthreads();
    }
    int e = blockIdx.x * 256 + t;          // 4096*32 total, grid.x = 512
    int r = e >> 5, c = e & 31;
    float v = 0.f;
    if (c < DBOX) {
        if (y == 0) v = box[r * DBOX + c];
        else {
            float s = 0.f;
#pragma unroll
            for (int k = 0; k < DBOX; ++k) s += box[r * DBOX + k] * Ms[k * DBOX + c];
            v = s;
        }
    }
    __half h = __float2half(v);
    if (y == 0) g_boxb[e] = h;
    else g_BMb[y - 1][e] = h;
}

// ================= projection: C[4096,256] = xb @ W  (mma.sync f16) ===============
__global__ void __launch_bounds__(256, 1) proj_kernel(int) {
    extern __shared__ char smem[];
    const int z = blockIdx.z;
    const int m0 = blockIdx.x * 128, n0 = blockIdx.y * 64;
    const int br = z / 3, wh = z % 3;
    __half* C = (wh == 0) ? g_Kb[br] : (wh == 1) ? g_Qb[br] : g_Vb[br];
    const __half* __restrict__ Wb = g_Wb[z];
    const int t = threadIdx.x, w = t >> 5, lane = t & 31;
    uint32_t sb = s2u(smem);
    const int mi = w >> 1, njw = w & 1;
    uint32_t acc[2][4][2] = {};

#define PROJ_ISSUE(ck)                                                               \
    {                                                                                \
        int k0 = (ck) * 64, buf = (ck) & 1;                                          \
        _Pragma("unroll") for (int l = 0; l < 4; ++l) {                              \
            int idx = t + l * 256;                                                   \
            int r = idx >> 3, c8 = (idx & 7) << 3;                                   \
            cp16(sb + buf * 18432 + (r * 72 + c8) * 2, g_xb + (m0 + r) * DIN + k0 + c8); \
        }                                                                            \
        _Pragma("unroll") for (int l = 0; l < 2; ++l) {                              \
            int idx = t + l * 256;                                                   \
            int r = idx >> 3, c8 = (idx & 7) << 3;                                   \
            cp16(sb + 36864 + buf * 9216 + (r * 72 + c8) * 2, Wb + (k0 + r) * HID + n0 + c8); \
        }                                                                            \
        CP_COMMIT;                                                                   \
    }

    PROJ_ISSUE(0);
    for (int ck = 0; ck < 8; ++ck) {
        if (ck < 7) { PROJ_ISSUE(ck + 1); CP_WAIT1; } else { CP_WAIT0; }
        __syncthreads();
        const uint32_t aB = sb + (ck & 1) * 18432;
        const uint32_t bB = sb + 36864 + (ck & 1) * 9216;
#pragma unroll
        for (int kt = 0; kt < 4; ++kt) {
            uint32_t a[2][4];
#pragma unroll
            for (int mt = 0; mt < 2; ++mt) {
                int row = mi * 32 + mt * 16 + (lane & 15);
                int col = kt * 16 + ((lane >> 4) << 3);
                ldsm4(a[mt], aB + (row * 72 + col) * 2);
            }
#pragma unroll
            for (int nb = 0; nb < 2; ++nb) {
                uint32_t bw[4];
                int wrow = kt * 16 + ((lane >> 3) & 1) * 8 + (lane & 7);
                int wcol = njw * 32 + nb * 16 + ((lane >> 4) << 3);
                ldsm4t(bw, bB + (wrow * 72 + wcol) * 2);
#pragma unroll
                for (int mt = 0; mt < 2; ++mt) {
                    mma16816h(acc[mt][nb * 2],     a[mt], bw);
                    mma16816h(acc[mt][nb * 2 + 1], a[mt], bw + 2);
                }
            }
        }
        __syncthreads();
    }
#pragma unroll
    for (int mt = 0; mt < 2; ++mt)
#pragma unroll
        for (int nt = 0; nt < 4; ++nt) {
            int row = m0 + mi * 32 + mt * 16 + (lane >> 2);
            int col = n0 + njw * 32 + nt * 8 + (lane & 3) * 2;
            *(uint32_t*)&C[row * HID + col]       = acc[mt][nt][0];
            *(uint32_t*)&C[(row + 8) * HID + col] = acc[mt][nt][1];
        }
}

// ================= fused attention: 64-row tiles, hoisted K/BM A-fragments ========
// 8 warps: mi = w>>1 (m16 rows), jh2 = w&1 (j32 k-slice in both GEMMs).
// smem map (bytes):
//   sK   [64][264] @0        33792
//   sBM  [64][40]  @33792     5120
//   sQ 2x[64][264] @38912    67584   (reused as O-reduce buffer [64][256] f32)
//   sBox 2x[64][40]@106496   10240
//   sV 2x[64][264] @116736   67584
//   sred           @184320    1024   -> total 185344
__global__ void __launch_bounds__(256, 1) attn_kernel(int) {
    extern __shared__ char smem[];
    const int b = blockIdx.y;
    const int i0 = blockIdx.x * 64;
    const int t = threadIdx.x, w = t >> 5, lane = t & 31;
    uint32_t sb = s2u(smem);
    const __half* __restrict__ Kg = g_Kb[b];
    const __half* __restrict__ Qg = g_Qb[b];
    const __half* __restrict__ Vg = g_Vb[b];
    const __half* __restrict__ BMg = g_BMb[b];

    const int mi = w >> 1, jh2 = w & 1;
    uint32_t acc[32][2] = {};       // O-partial: m16 x d256 (f16 packed)
    uint32_t ka[16][4];             // hoisted K A-frags: m16 x k256
    uint32_t agm[2][4];             // hoisted BM A-frags: m16 x k32
    float sumLoc = 0.f;

    // ---- prologue loads ----
#pragma unroll
    for (int l = 0; l < 8; ++l) {
        int idx = t + l * 256;
        int r = idx >> 5, c8 = (idx & 31) << 3;
        cp16(sb + (r * 264 + c8) * 2, Kg + (i0 + r) * HID + c8);
    }
    { int r = t >> 2, c8 = (t & 3) << 3;
      cp16(sb + 33792 + (r * 40 + c8) * 2, BMg + (i0 + r) * 32 + c8); }
    CP_COMMIT;

#define ATTN_ISSUE(j0, buf)                                                          \
    {                                                                                \
        _Pragma("unroll") for (int l = 0; l < 8; ++l) {                              \
            int idx = t + l * 256;                                                   \
            int r = idx >> 5, c8 = (idx & 31) << 3;                                  \
            cp16(sb + 38912 + (buf) * 33792 + (r * 264 + c8) * 2, Qg + ((j0) + r) * HID + c8); \
        }                                                                            \
        _Pragma("unroll") for (int l = 0; l < 8; ++l) {                              \
            int idx = t + l * 256;                                                   \
            int r = idx >> 5, c8 = (idx & 31) << 3;                                  \
            cp16(sb + 116736 + (buf) * 33792 + (r * 264 + c8) * 2, Vg + ((j0) + r) * HID + c8); \
        }                                                                            \
        { int r = t >> 2, c8 = (t & 3) << 3;                                         \
          cp16(sb + 106496 + (buf) * 5120 + (r * 40 + c8) * 2, g_boxb + ((j0) + r) * 32 + c8); } \
        CP_COMMIT;                                                                   \
    }
    ATTN_ISSUE(0, 0);
    ATTN_ISSUE(64, 1);

#pragma unroll 1
    for (int jt = 0; jt < 64; ++jt) {
        const int cur = jt & 1;
        CP_WAIT1;                  // tiles for jt (and K/BM on jt=0) resident
        __syncthreads();
        const uint32_t qB = sb + 38912 + cur * 33792;
        const uint32_t xB = sb + 106496 + cur * 5120;
        const uint32_t vB = sb + 116736 + cur * 33792;

        if (jt == 0) {             // hoist K + BM A-frags into persistent registers
#pragma unroll
            for (int kt = 0; kt < 16; ++kt) {
                int row = mi * 16 + (lane & 15);
                int col = kt * 16 + ((lane >> 4) << 3);
                ldsm4(ka[kt], sb + (row * 264 + col) * 2);
            }
#pragma unroll
            for (int kt = 0; kt < 2; ++kt) {
                int row = mi * 16 + (lane & 15);
                int col = kt * 16 + ((lane >> 4) << 3);
                ldsm4(agm[kt], sb + 33792 + (row * 40 + col) * 2);
            }
        }

        // ---- stage 1: wa = K_i . Q_j^T (k=256), A from registers ----
        uint32_t wa[4][2] = {};
        uint32_t gg[4][2] = {};
        const int brow = jh2 * 32 + ((lane >> 4) << 3) + (lane & 7);
#pragma unroll
        for (int kt = 0; kt < 16; ++kt) {
            uint32_t bq0[4], bq1[4];
            int bcol = kt * 16 + ((lane >> 3) & 1) * 8;
            ldsm4(bq0, qB + (brow * 264 + bcol) * 2);
            ldsm4(bq1, qB + ((brow + 16) * 264 + bcol) * 2);
            mma16816h(wa[0], ka[kt], bq0);
            mma16816h(wa[1], ka[kt], bq0 + 2);
            mma16816h(wa[2], ka[kt], bq1);
            mma16816h(wa[3], ka[kt], bq1 + 2);
        }
        // ---- gate: gg = BM_i . box_j^T (k=32), A from registers ----
#pragma unroll
        for (int kt = 0; kt < 2; ++kt) {
            uint32_t bx0[4], bx1[4];
            int bcol = kt * 16 + ((lane >> 3) & 1) * 8;
            ldsm4(bx0, xB + (brow * 40 + bcol) * 2);
            ldsm4(bx1, xB + ((brow + 16) * 40 + bcol) * 2);
            mma16816h(gg[0], agm[kt], bx0);
            mma16816h(gg[1], agm[kt], bx0 + 2);
            mma16816h(gg[2], agm[kt], bx1);
            mma16816h(gg[3], agm[kt], bx1 + 2);
        }

        // ---- elementwise in regs: S = relu(G/16) * exp(WA/16); pack to A-frags ----
        uint32_t sf[2][4];
#pragma unroll
        for (int nb = 0; nb < 4; ++nb) {
            float2 a01 = unpackh2(wa[nb][0]), a23 = unpackh2(wa[nb][1]);
            float2 g01 = unpackh2(gg[nb][0]), g23 = unpackh2(gg[nb][1]);
            float s0 = g01.x > 0.f ? g01.x * 0.0625f * __expf(a01.x * 0.0625f) : 0.f;
            float s1 = g01.y > 0.f ? g01.y * 0.0625f * __expf(a01.y * 0.0625f) : 0.f;
            float s2 = g23.x > 0.f ? g23.x * 0.0625f * __expf(a23.x * 0.0625f) : 0.f;
            float s3 = g23.y > 0.f ? g23.y * 0.0625f * __expf(a23.y * 0.0625f) : 0.f;
            sumLoc += (s0 + s1) + (s2 + s3);
            sf[nb >> 1][(nb & 1) * 2]     = packh2(s0, s1);
            sf[nb >> 1][(nb & 1) * 2 + 1] = packh2(s2, s3);
        }

        // ---- stage 2: O-partial += S(m16 x j32) @ V(j32 x d256) ----
#pragma unroll
        for (int kt2 = 0; kt2 < 2; ++kt2) {
            int vrow = jh2 * 32 + kt2 * 16 + ((lane >> 3) & 1) * 8 + (lane & 7);
#pragma unroll
            for (int nb = 0; nb < 16; ++nb) {
                uint32_t bv[4];
                int vcol = nb * 16 + ((lane >> 4) << 3);
                ldsm4t(bv, vB + (vrow * 264 + vcol) * 2);
                mma16816h(acc[nb * 2],     sf[kt2], bv);
                mma16816h(acc[nb * 2 + 1], sf[kt2], bv + 2);
            }
        }
        __syncthreads();           // all warps done with buf 'cur'
        ATTN_ISSUE(((jt + 2) & 63) * 64, cur);
    }

    // ---- epilogue: cross-pair O reduce (j-halves) via smem, write g_O ----
    CP_WAIT0;
    __syncthreads();
    float* smemO = (float*)(smem + 38912);    // [64][256] f32
    if (jh2 == 0) {
#pragma unroll
        for (int nb = 0; nb < 32; ++nb) {
            int row = mi * 16 + (lane >> 2);
            int col = nb * 8 + (lane & 3) * 2;
            *(float2*)&smemO[row * 256 + col]       = unpackh2(acc[nb][0]);
            *(float2*)&smemO[(row + 8) * 256 + col] = unpackh2(acc[nb][1]);
        }
    }
    __syncthreads();
    if (jh2 == 1) {
#pragma unroll
        for (int nb = 0; nb < 32; ++nb) {
            int row = mi * 16 + (lane >> 2);
            int col = nb * 8 + (lane & 3) * 2;
            float2 q0 = unpackh2(acc[nb][0]);
            float2 q1 = unpackh2(acc[nb][1]);
            float2 p0 = *(float2*)&smemO[row * 256 + col];
            float2 p1 = *(float2*)&smemO[(row + 8) * 256 + col];
            *(float2*)&g_O[b][(i0 + row) * HID + col] =
                make_float2(p0.x + q0.x, p0.y + q0.y);
            *(float2*)&g_O[b][(i0 + row + 8) * HID + col] =
                make_float2(p1.x + q1.x, p1.y + q1.y);
        }
    }

    // ---- deterministic partial sum ----
    float* sred = (float*)(smem + 184320);
    sred[t] = sumLoc;
    __syncthreads();
    for (int s2 = 128; s2 > 0; s2 >>= 1) {
        if (t < s2) sred[t] += sred[t + s2];
        __syncthreads();
    }
    if (t == 0) g_part[b][blockIdx.x] = sred[0];
}

// ================= final sum -> 0.1/sum ===========================================
__global__ void sum_kernel() {
    if (threadIdx.x == 0) {
        float s = 0.f;
        for (int i = 0; i < 64; ++i) s += g_part[blockIdx.x][i];
        g_isum[blockIdx.x] = 0.1f / s;
    }
}

// ================= out = x + 0.1 * O/sum ==========================================
__global__ __launch_bounds__(256) void final_kernel(const float* __restrict__ x,
                                                    float* __restrict__ out) {
    int idx = blockIdx.x * 256 + threadIdx.x;
    int r = idx >> 9, c = idx & 511;
    int b = c >> 8, cc = c & 255;
    out[idx] = fmaf(g_O[b][r * HID + cc], g_isum[b], x[idx]);
}

// =================================================================================
extern "C" void kernel_launch(void* const* d_in, const int* in_sizes, int n_in,
                              void* d_out, int out_size) {
    const float* x   = (const float*)d_in[0];
    const float* box = (const float*)d_in[1];
    const float* WG1 = (const float*)d_in[2];
    const float* WK1 = (const float*)d_in[3];
    const float* WQ1 = (const float*)d_in[4];
    const float* WV1 = (const float*)d_in[5];
    const float* WG2 = (const float*)d_in[6];
    const float* WK2 = (const float*)d_in[7];
    const float* WQ2 = (const float*)d_in[8];
    const float* WV2 = (const float*)d_in[9];
    float* out = (float*)d_out;

    static int inited = 0;
    if (!inited) {
        cudaFuncSetAttribute(proj_kernel, cudaFuncAttributeMaxDynamicSharedMemorySize, 55296);
        cudaFuncSetAttribute(attn_kernel, cudaFuncAttributeMaxDynamicSharedMemorySize, 185344);
        inited = 1;
    }

    conv_x<<<2048, 256>>>(x);
    conv_w<<<dim3(128, 1, 6), 256>>>(WK1, WQ1, WV1, WK2, WQ2, WV2);
    gramm_kernel<<<2, 512>>>(WG1, WG2);
    pad_kernel<<<dim3(512, 3), 256>>>(box);
    proj_kernel<<<dim3(32, 4, 6), 256, 55296>>>(0);
    attn_kernel<<<dim3(64, 2), 256, 185344>>>(0);
    sum_kernel<<<2, 32>>>();
    final_kernel<<<8192, 256>>>(x, out);
}

// round 17
// speedup vs baseline: 1.9224x; 1.1317x over previous
#include <cuda_runtime.h>
#include <cuda_fp16.h>
#include <cstdint>

#define NN   4096
#define DIN  512
#define HID  256
#define DBOX 22

// ---- scratch (device globals) ----
__device__ __half g_xb[NN * DIN];
__device__ __half g_Wb[6][DIN * HID];    // W in f16, [k][n] as given
__device__ __half g_Kb[2][NN * HID];
__device__ __half g_Qb[2][NN * HID];
__device__ __half g_Vb[2][NN * HID];
__device__ __half g_BMb[2][NN * 32];     // box@M, zero-padded to 32 cols
__device__ __half g_boxb[NN * 32];       // box, zero-padded to 32 cols
__device__ float g_M[2][DBOX * DBOX];
__device__ float g_Opart[2][2][NN * HID];  // per-branch, per-jhalf partial O
__device__ float g_part[2][128];
__device__ float g_isum[2];

// ================= PTX helpers =====================================================
__device__ __forceinline__ uint32_t s2u(const void* p) {
    uint32_t a;
    asm("{ .reg .u64 t; cvta.to.shared.u64 t, %1; cvt.u32.u64 %0, t; }" : "=r"(a) : "l"(p));
    return a;
}
__device__ __forceinline__ void cp16(uint32_t s, const void* g) {
    asm volatile("cp.async.cg.shared.global [%0], [%1], 16;" :: "r"(s), "l"(g));
}
#define CP_COMMIT asm volatile("cp.async.commit_group;" ::: "memory")
#define CP_WAIT0  asm volatile("cp.async.wait_group 0;"  ::: "memory")
#define CP_WAIT1  asm volatile("cp.async.wait_group 1;"  ::: "memory")

__device__ __forceinline__ void ldsm4(uint32_t* r, uint32_t a) {
    asm volatile("ldmatrix.sync.aligned.m8n8.x4.shared.b16 {%0,%1,%2,%3}, [%4];"
                 : "=r"(r[0]), "=r"(r[1]), "=r"(r[2]), "=r"(r[3]) : "r"(a));
}
__device__ __forceinline__ void ldsm4t(uint32_t* r, uint32_t a) {
    asm volatile("ldmatrix.sync.aligned.m8n8.x4.trans.shared.b16 {%0,%1,%2,%3}, [%4];"
                 : "=r"(r[0]), "=r"(r[1]), "=r"(r[2]), "=r"(r[3]) : "r"(a));
}
// f16 x f16 -> f16 acc (packed half2 accumulators, 2 regs)
__device__ __forceinline__ void mma16816h(uint32_t* d, const uint32_t* a, const uint32_t* b) {
    asm volatile(
        "mma.sync.aligned.m16n8k16.row.col.f16.f16.f16.f16 "
        "{%0,%1}, {%2,%3,%4,%5}, {%6,%7}, {%0,%1};"
        : "+r"(d[0]), "+r"(d[1])
        : "r"(a[0]), "r"(a[1]), "r"(a[2]), "r"(a[3]), "r"(b[0]), "r"(b[1]));
}
__device__ __forceinline__ uint32_t packh2(float x, float y) {
    __half2 h = __floats2half2_rn(x, y);
    return *(uint32_t*)&h;
}
__device__ __forceinline__ float2 unpackh2(uint32_t u) {
    return __half22float2(*(__half2*)&u);
}

// ================= conversions (known-good, separate launches) ====================
__global__ __launch_bounds__(256) void conv_x(const float* __restrict__ x) {
    int idx = blockIdx.x * 256 + threadIdx.x;          // float4 index
    float4 v = ((const float4*)x)[idx];
    *(uint32_t*)&g_xb[idx * 4]     = packh2(v.x, v.y);
    *(uint32_t*)&g_xb[idx * 4 + 2] = packh2(v.z, v.w);
}

__global__ __launch_bounds__(256) void conv_w(
    const float* __restrict__ W0, const float* __restrict__ W1, const float* __restrict__ W2,
    const float* __restrict__ W3, const float* __restrict__ W4, const float* __restrict__ W5) {
    const int z = blockIdx.z;
    const float* W = (z == 0) ? W0 : (z == 1) ? W1 : (z == 2) ? W2 : (z == 3) ? W3 : (z == 4) ? W4 : W5;
    int idx = blockIdx.x * 256 + threadIdx.x;
    float4 v = ((const float4*)W)[idx];
    *(uint32_t*)&g_Wb[z][idx * 4]     = packh2(v.x, v.y);
    *(uint32_t*)&g_Wb[z][idx * 4 + 2] = packh2(v.z, v.w);
}

// ================= M = WG @ WG^T (22x22, fp32) ====================================
__global__ void gramm_kernel(const float* __restrict__ WG1, const float* __restrict__ WG2) {
    const float* WG = blockIdx.x ? WG2 : WG1;
    int t = threadIdx.x;
    if (t < DBOX * DBOX) {
        int i = t / DBOX, j = t % DBOX;
        float s = 0.f;
        for (int d = 0; d < HID; ++d) s += WG[i * HID + d] * WG[j * HID + d];
        g_M[blockIdx.x][t] = s;
    }
}

// ================= pad box / BM -> [4096,32] f16 ==================================
__global__ __launch_bounds__(256) void pad_kernel(const float* __restrict__ box) {
    __shared__ float Ms[DBOX * DBOX];
    int y = blockIdx.y, t = threadIdx.x;   // y: 0=box, 1=BM br0, 2=BM br1
    if (y > 0) {
        for (int i = t; i < DBOX * DBOX; i += 256) Ms[i] = g_M[y - 1][i];
        __syncthreads();
    }
    int e = blockIdx.x * 256 + t;          // 4096*32 total, grid.x = 512
    int r = e >> 5, c = e & 31;
    float v = 0.f;
    if (c < DBOX) {
        if (y == 0) v = box[r * DBOX + c];
        else {
            float s = 0.f;
#pragma unroll
            for (int k = 0; k < DBOX; ++k) s += box[r * DBOX + k] * Ms[k * DBOX + c];
            v = s;
        }
    }
    __half h = __float2half(v);
    if (y == 0) g_boxb[e] = h;
    else g_BMb[y - 1][e] = h;
}

// ================= projection: C[4096,256] = xb @ W  (mma.sync f16) ===============
__global__ void __launch_bounds__(256, 1) proj_kernel(int) {
    extern __shared__ char smem[];
    const int z = blockIdx.z;
    const int m0 = blockIdx.x * 128, n0 = blockIdx.y * 64;
    const int br = z / 3, wh = z % 3;
    __half* C = (wh == 0) ? g_Kb[br] : (wh == 1) ? g_Qb[br] : g_Vb[br];
    const __half* __restrict__ Wb = g_Wb[z];
    const int t = threadIdx.x, w = t >> 5, lane = t & 31;
    uint32_t sb = s2u(smem);
    const int mi = w >> 1, njw = w & 1;
    uint32_t acc[2][4][2] = {};

#define PROJ_ISSUE(ck)                                                               \
    {                                                                                \
        int k0 = (ck) * 64, buf = (ck) & 1;                                          \
        _Pragma("unroll") for (int l = 0; l < 4; ++l) {                              \
            int idx = t + l * 256;                                                   \
            int r = idx >> 3, c8 = (idx & 7) << 3;                                   \
            cp16(sb + buf * 18432 + (r * 72 + c8) * 2, g_xb + (m0 + r) * DIN + k0 + c8); \
        }                                                                            \
        _Pragma("unroll") for (int l = 0; l < 2; ++l) {                              \
            int idx = t + l * 256;                                                   \
            int r = idx >> 3, c8 = (idx & 7) << 3;                                   \
            cp16(sb + 36864 + buf * 9216 + (r * 72 + c8) * 2, Wb + (k0 + r) * HID + n0 + c8); \
        }                                                                            \
        CP_COMMIT;                                                                   \
    }

    PROJ_ISSUE(0);
    for (int ck = 0; ck < 8; ++ck) {
        if (ck < 7) { PROJ_ISSUE(ck + 1); CP_WAIT1; } else { CP_WAIT0; }
        __syncthreads();
        const uint32_t aB = sb + (ck & 1) * 18432;
        const uint32_t bB = sb + 36864 + (ck & 1) * 9216;
#pragma unroll
        for (int kt = 0; kt < 4; ++kt) {
            uint32_t a[2][4];
#pragma unroll
            for (int mt = 0; mt < 2; ++mt) {
                int row = mi * 32 + mt * 16 + (lane & 15);
                int col = kt * 16 + ((lane >> 4) << 3);
                ldsm4(a[mt], aB + (row * 72 + col) * 2);
            }
#pragma unroll
            for (int nb = 0; nb < 2; ++nb) {
                uint32_t bw[4];
                int wrow = kt * 16 + ((lane >> 3) & 1) * 8 + (lane & 7);
                int wcol = njw * 32 + nb * 16 + ((lane >> 4) << 3);
                ldsm4t(bw, bB + (wrow * 72 + wcol) * 2);
#pragma unroll
                for (int mt = 0; mt < 2; ++mt) {
                    mma16816h(acc[mt][nb * 2],     a[mt], bw);
                    mma16816h(acc[mt][nb * 2 + 1], a[mt], bw + 2);
                }
            }
        }
        __syncthreads();
    }
#pragma unroll
    for (int mt = 0; mt < 2; ++mt)
#pragma unroll
        for (int nt = 0; nt < 4; ++nt) {
            int row = m0 + mi * 32 + mt * 16 + (lane >> 2);
            int col = n0 + njw * 32 + nt * 8 + (lane & 3) * 2;
            *(uint32_t*)&C[row * HID + col]       = acc[mt][nt][0];
            *(uint32_t*)&C[(row + 8) * HID + col] = acc[mt][nt][1];
        }
}

// ================= fused attention: i64 tile, j-range split across 2 co-res CTAs ==
// grid (64, 2, 2): x = i-tile, y = branch, z = j-half. 128 threads, 4 warps.
// Warp w owns m16 rows [w*16, w*16+16); each warp computes full j32 per tile.
// No intra-CTA j-split -> no cross-warp O reduce; O written as gmem partials.
// smem map (bytes):
//   sK   [64][264] @0        33792
//   sBM  [64][40]  @33792     5120
//   sQ 2x[32][264] @38912    33792
//   sBox 2x[32][40]@72704     5120
//   sV 2x[32][264] @77824    33792
//   sred           @111616     512   -> total 112128 (x2 CTAs = 224256/SM)
__global__ void __launch_bounds__(128, 2) attn_kernel(int) {
    extern __shared__ char smem[];
    const int b = blockIdx.y, jz = blockIdx.z;
    const int i0 = blockIdx.x * 64;
    const int jbase = jz * 2048;
    const int t = threadIdx.x, w = t >> 5, lane = t & 31;
    uint32_t sb = s2u(smem);
    const __half* __restrict__ Kg = g_Kb[b];
    const __half* __restrict__ Qg = g_Qb[b];
    const __half* __restrict__ Vg = g_Vb[b];
    const __half* __restrict__ BMg = g_BMb[b];

    const int mi = w;
    uint32_t acc[32][2] = {};       // O-partial: m16 x d256 (f16 packed)
    uint32_t ka[16][4];             // hoisted K A-frags: m16 x k256
    uint32_t agm[2][4];             // hoisted BM A-frags: m16 x k32
    float sumLoc = 0.f;

    // ---- prologue: K (64x256) + BM (64x32) ----
#pragma unroll
    for (int l = 0; l < 16; ++l) {
        int idx = t + l * 128;
        int r = idx >> 5, c8 = (idx & 31) << 3;
        cp16(sb + (r * 264 + c8) * 2, Kg + (i0 + r) * HID + c8);
    }
#pragma unroll
    for (int l = 0; l < 2; ++l) {
        int idx = t + l * 128;
        int r = idx >> 2, c8 = (idx & 3) << 3;
        cp16(sb + 33792 + (r * 40 + c8) * 2, BMg + (i0 + r) * 32 + c8);
    }
    CP_COMMIT;

#define ATTN_ISSUE(j0, buf)                                                          \
    {                                                                                \
        _Pragma("unroll") for (int l = 0; l < 8; ++l) {                              \
            int idx = t + l * 128;                                                   \
            int r = idx >> 5, c8 = (idx & 31) << 3;                                  \
            cp16(sb + 38912 + (buf) * 16896 + (r * 264 + c8) * 2, Qg + ((j0) + r) * HID + c8); \
        }                                                                            \
        _Pragma("unroll") for (int l = 0; l < 8; ++l) {                              \
            int idx = t + l * 128;                                                   \
            int r = idx >> 5, c8 = (idx & 31) << 3;                                  \
            cp16(sb + 77824 + (buf) * 16896 + (r * 264 + c8) * 2, Vg + ((j0) + r) * HID + c8); \
        }                                                                            \
        { int r = t >> 2, c8 = (t & 3) << 3;                                         \
          cp16(sb + 72704 + (buf) * 2560 + (r * 40 + c8) * 2, g_boxb + ((j0) + r) * 32 + c8); } \
        CP_COMMIT;                                                                   \
    }
    ATTN_ISSUE(jbase, 0);
    ATTN_ISSUE(jbase + 32, 1);

#pragma unroll 1
    for (int jt = 0; jt < 64; ++jt) {
        const int cur = jt & 1;
        CP_WAIT1;                  // tile jt (and K/BM on jt=0) resident
        __syncthreads();
        const uint32_t qB = sb + 38912 + cur * 16896;
        const uint32_t xB = sb + 72704 + cur * 2560;
        const uint32_t vB = sb + 77824 + cur * 16896;

        if (jt == 0) {             // hoist K + BM A-frags into persistent registers
#pragma unroll
            for (int kt = 0; kt < 16; ++kt) {
                int row = mi * 16 + (lane & 15);
                int col = kt * 16 + ((lane >> 4) << 3);
                ldsm4(ka[kt], sb + (row * 264 + col) * 2);
            }
#pragma unroll
            for (int kt = 0; kt < 2; ++kt) {
                int row = mi * 16 + (lane & 15);
                int col = kt * 16 + ((lane >> 4) << 3);
                ldsm4(agm[kt], sb + 33792 + (row * 40 + col) * 2);
            }
        }

        // ---- stage 1: wa = K_i . Q_j^T (k=256) over j32 ----
        uint32_t wa[4][2] = {};
        uint32_t gg[4][2] = {};
        const int brow = ((lane >> 4) << 3) + (lane & 7);
#pragma unroll
        for (int kt = 0; kt < 16; ++kt) {
            uint32_t bq0[4], bq1[4];
            int bcol = kt * 16 + ((lane >> 3) & 1) * 8;
            ldsm4(bq0, qB + (brow * 264 + bcol) * 2);
            ldsm4(bq1, qB + ((brow + 16) * 264 + bcol) * 2);
            mma16816h(wa[0], ka[kt], bq0);
            mma16816h(wa[1], ka[kt], bq0 + 2);
            mma16816h(wa[2], ka[kt], bq1);
            mma16816h(wa[3], ka[kt], bq1 + 2);
        }
        // ---- gate: gg = BM_i . box_j^T (k=32) ----
#pragma unroll
        for (int kt = 0; kt < 2; ++kt) {
            uint32_t bx0[4], bx1[4];
            int bcol = kt * 16 + ((lane >> 3) & 1) * 8;
            ldsm4(bx0, xB + (brow * 40 + bcol) * 2);
            ldsm4(bx1, xB + ((brow + 16) * 40 + bcol) * 2);
            mma16816h(gg[0], agm[kt], bx0);
            mma16816h(gg[1], agm[kt], bx0 + 2);
            mma16816h(gg[2], agm[kt], bx1);
            mma16816h(gg[3], agm[kt], bx1 + 2);
        }

        // ---- elementwise in regs: S = relu(G/16) * exp(WA/16); pack to A-frags ----
        uint32_t sf[2][4];
#pragma unroll
        for (int nb = 0; nb < 4; ++nb) {
            float2 a01 = unpackh2(wa[nb][0]), a23 = unpackh2(wa[nb][1]);
            float2 g01 = unpackh2(gg[nb][0]), g23 = unpackh2(gg[nb][1]);
            float s0 = g01.x > 0.f ? g01.x * 0.0625f * __expf(a01.x * 0.0625f) : 0.f;
            float s1 = g01.y > 0.f ? g01.y * 0.0625f * __expf(a01.y * 0.0625f) : 0.f;
            float s2 = g23.x > 0.f ? g23.x * 0.0625f * __expf(a23.x * 0.0625f) : 0.f;
            float s3 = g23.y > 0.f ? g23.y * 0.0625f * __expf(a23.y * 0.0625f) : 0.f;
            sumLoc += (s0 + s1) + (s2 + s3);
            sf[nb >> 1][(nb & 1) * 2]     = packh2(s0, s1);
            sf[nb >> 1][(nb & 1) * 2 + 1] = packh2(s2, s3);
        }

        // ---- stage 2: O-partial += S(m16 x j32) @ V(j32 x d256) ----
#pragma unroll
        for (int kt2 = 0; kt2 < 2; ++kt2) {
            int vrow = kt2 * 16 + ((lane >> 3) & 1) * 8 + (lane & 7);
#pragma unroll
            for (int nb = 0; nb < 16; ++nb) {
                uint32_t bv[4];
                int vcol = nb * 16 + ((lane >> 4) << 3);
                ldsm4t(bv, vB + (vrow * 264 + vcol) * 2);
                mma16816h(acc[nb * 2],     sf[kt2], bv);
                mma16816h(acc[nb * 2 + 1], sf[kt2], bv + 2);
            }
        }
        __syncthreads();           // all warps done with buf 'cur'
        ATTN_ISSUE(jbase + ((jt + 2) & 63) * 32, cur);
    }

    // ---- epilogue: each warp owns its m16 rows -> write partial O directly ----
    CP_WAIT0;
    float* dst = g_Opart[b][jz];
#pragma unroll
    for (int nb = 0; nb < 32; ++nb) {
        int row = i0 + mi * 16 + (lane >> 2);
        int col = nb * 8 + (lane & 3) * 2;
        *(float2*)&dst[row * HID + col]       = unpackh2(acc[nb][0]);
        *(float2*)&dst[(row + 8) * HID + col] = unpackh2(acc[nb][1]);
    }

    // ---- deterministic partial sum ----
    float* sred = (float*)(smem + 111616);
    sred[t] = sumLoc;
    __syncthreads();
    for (int s2 = 64; s2 > 0; s2 >>= 1) {
        if (t < s2) sred[t] += sred[t + s2];
        __syncthreads();
    }
    if (t == 0) g_part[b][jz * 64 + blockIdx.x] = sred[0];
}

// ================= final sum -> 0.1/sum ===========================================
__global__ void sum_kernel() {
    if (threadIdx.x == 0) {
        float s = 0.f;
        for (int i = 0; i < 128; ++i) s += g_part[blockIdx.x][i];
        g_isum[blockIdx.x] = 0.1f / s;
    }
}

// ================= out = x + 0.1 * (O0+O1)/sum ====================================
__global__ __launch_bounds__(256) void final_kernel(const float* __restrict__ x,
                                                    float* __restrict__ out) {
    int idx = blockIdx.x * 256 + threadIdx.x;
    int r = idx >> 9, c = idx & 511;
    int b = c >> 8, cc = c & 255;
    float o = g_Opart[b][0][r * HID + cc] + g_Opart[b][1][r * HID + cc];
    out[idx] = fmaf(o, g_isum[b], x[idx]);
}

// =================================================================================
extern "C" void kernel_launch(void* const* d_in, const int* in_sizes, int n_in,
                              void* d_out, int out_size) {
    const float* x   = (const float*)d_in[0];
    const float* box = (const float*)d_in[1];
    const float* WG1 = (const float*)d_in[2];
    const float* WK1 = (const float*)d_in[3];
    const float* WQ1 = (const float*)d_in[4];
    const float* WV1 = (const float*)d_in[5];
    const float* WG2 = (const float*)d_in[6];
    const float* WK2 = (const float*)d_in[7];
    const float* WQ2 = (const float*)d_in[8];
    const float* WV2 = (const float*)d_in[9];
    float* out = (float*)d_out;

    static int inited = 0;
    if (!inited) {
        cudaFuncSetAttribute(proj_kernel, cudaFuncAttributeMaxDynamicSharedMemorySize, 55296);
        cudaFuncSetAttribute(attn_kernel, cudaFuncAttributeMaxDynamicSharedMemorySize, 112128);
        inited = 1;
    }

    conv_x<<<2048, 256>>>(x);
    conv_w<<<dim3(128, 1, 6), 256>>>(WK1, WQ1, WV1, WK2, WQ2, WV2);
    gramm_kernel<<<2, 512>>>(WG1, WG2);
    pad_kernel<<<dim3(512, 3), 256>>>(box);
    proj_kernel<<<dim3(32, 4, 6), 256, 55296>>>(0);
    attn_kernel<<<dim3(64, 2, 2), 128, 112128>>>(0);
    sum_kernel<<<2, 32>>>();
    final_kernel<<<8192, 256>>>(x, out);
}